// round 12
// baseline (speedup 1.0000x reference)
#include <cuda_runtime.h>
#include <cstdint>

// Problem constants
#define NN    8192
#define NP1   8193
#define AB    16384ULL                    // A_low base (floats)
#define MM    67125249ULL                 // NP1*NP1
#define AUB   67141633ULL                 // A_up base = AB + MM
#define LR0   134258689ULL                // A_up last-row start (floats)

// Edges kernel: disjoint from the memset range [AB, LR0):
//   [0, 16384)      : conc_low | conc_up head   (coalesced)
//   [16384, 24577)  : A_up last row col 0..8192 (coalesced; col 8192 -> 1)
#define E_HEAD  16384
#define E_TOT   (E_HEAD + NP1)            // 24577

// Diag kernel: inside the memset range, runs after it:
//   [0, 8193)       : A_low diagonal k = 0..8192 (k = 8192 -> 1)
//   [8193, 16385)   : A_up diagonal  k = 0..8191
#define D_SPLIT NP1
#define D_TOT   (D_SPLIT + NN)            // 16385

#define THREADS 512

__global__ void __launch_bounds__(THREADS) relu_patch_edges(
        const float* __restrict__ lower,
        const float* __restrict__ upper,
        const float* __restrict__ alphas,
        float* __restrict__ out) {
    const int w = blockIdx.x * THREADS + threadIdx.x;
    if (w >= E_TOT) return;

    if (w < E_HEAD) {
        // conc_low / conc_up (coalesced)
        const int i = w & (NN - 1);
        const float l = lower[i];
        const float u = upper[i];
        float val;
        if (w < NN) {
            const float a = fminf(fmaxf(alphas[i], 0.f), 1.f);
            val = (u > 0.f) ? ((l >= 0.f) ? l : a * l) : 0.f;
        } else {
            val = (u > 0.f) ? u : 0.f;
        }
        out[w] = val;
    } else {
        // A_up last row (bias_up); col NN -> 1.0
        const int col = w - E_HEAD;
        float val;
        if (col == NN) {
            val = 1.f;
        } else {
            const float l = lower[col];
            const float u = upper[col];
            const float d = u - l;
            const float lam = u / ((d == 0.f) ? 1.f : d);
            val = ((u > 0.f) && (l < 0.f)) ? (-lam * l) : 0.f;
        }
        out[LR0 + (size_t)col] = val;
    }
}

__global__ void __launch_bounds__(THREADS) relu_patch_diag(
        const float* __restrict__ lower,
        const float* __restrict__ upper,
        const float* __restrict__ alphas,
        float* __restrict__ out) {
    const int w = blockIdx.x * THREADS + threadIdx.x;
    if (w >= D_TOT) return;

    size_t pos;
    float  val;
    if (w < D_SPLIT) {
        const int k = w;                               // A_low diag, k = 0..8192
        if (k == NN) {
            val = 1.f;
        } else {
            const float l = lower[k];
            const float u = upper[k];
            const float a = fminf(fmaxf(alphas[k], 0.f), 1.f);
            val = (u > 0.f) ? ((l >= 0.f) ? 1.f : a) : 0.f;
        }
        pos = AB + (size_t)k * (size_t)(NP1 + 1);
    } else {
        const int k = w - D_SPLIT;                     // A_up diag, k = 0..8191
        const float l = lower[k];
        const float u = upper[k];
        const float d = u - l;
        const float lam = u / ((d == 0.f) ? 1.f : d);
        val = (u > 0.f) ? ((l >= 0.f) ? 1.f : lam) : 0.f;
        pos = AUB + (size_t)k * (size_t)(NP1 + 1);
    }
    __stcs(out + pos, val);   // scattered streaming store (best measured)
}

// Streams/events created once at load; no device-memory allocation.
// kernel_launch issues identical work every call (graph-capture safe).
namespace {
struct ForkCtx {
    cudaStream_t sE;
    cudaEvent_t  eRoot, eEdges;
    ForkCtx() {
        cudaStreamCreateWithFlags(&sE, cudaStreamNonBlocking);
        cudaEventCreateWithFlags(&eRoot,  cudaEventDisableTiming);
        cudaEventCreateWithFlags(&eEdges, cudaEventDisableTiming);
    }
};
ForkCtx g_fork;
}

extern "C" void kernel_launch(void* const* d_in, const int* in_sizes, int n_in,
                              void* d_out, int out_size) {
    const float* lower  = (const float*)d_in[0];
    const float* upper  = (const float*)d_in[1];
    const float* alphas = (const float*)d_in[2];
    float* out = (float*)d_out;

    // Fork point: edges kernel has NO dependency on the memset (disjoint bytes)
    // and overlaps it on a second stream.
    cudaEventRecord(g_fork.eRoot, 0);
    cudaStreamWaitEvent(g_fork.sE, g_fork.eRoot, 0);
    relu_patch_edges<<<(E_TOT + THREADS - 1) / THREADS, THREADS, 0, g_fork.sE>>>(
        lower, upper, alphas, out);
    cudaEventRecord(g_fork.eEdges, g_fork.sE);

    // Bulk zero of the matrix interior only: [AB, LR0) floats. The head and
    // A_up last row are excluded (written concurrently by the edges kernel).
    // Fast/slow memset mode is a per-run GPU state draw, independent of the
    // range (R10 vs R1/R5/R7/R11 — identical calls, both modes observed).
    cudaMemsetAsync((char*)d_out + AB * 4, 0, (LR0 - AB) * 4, 0);

    // Diagonals live inside the memset range: serialized after it.
    relu_patch_diag<<<(D_TOT + THREADS - 1) / THREADS, THREADS>>>(
        lower, upper, alphas, out);

    // Join the forked stream before capture ends.
    cudaStreamWaitEvent(0, g_fork.eEdges, 0);
}

// round 14
// speedup vs baseline: 1.0123x; 1.0123x over previous
#include <cuda_runtime.h>
#include <cstdint>

// Problem constants
#define NN    8192
#define NP1   8193
#define AB    16384ULL                    // A_low base (floats)
#define MM    67125249ULL                 // NP1*NP1
#define AUB   67141633ULL                 // A_up base = AB + MM
#define LR0   134258689ULL                // A_up last-row start (floats)

// Memset region: bytes [AB*4, LR0*4), total 536,969,220 B, split in 4 parallel
// nodes. First three quarters 134,242,304 B (16B-aligned), last takes the rest.
#define MS_BASE   (AB * 4ULL)             // 65536
#define MS_TOTAL  536969220ULL
#define MS_Q      134242304ULL            // quarters 0..2
#define MS_Q3     (MS_TOTAL - 3ULL * MS_Q) // 134242308

// Edges kernel (disjoint from memset range; overlaps it):
//   [0, 16384)      : conc_low | conc_up head
//   [16384, 24577)  : A_up last row col 0..8192 (col 8192 -> 1)
#define E_HEAD  16384
#define E_TOT   (E_HEAD + NP1)            // 24577

// Diag kernel (inside memset range; serialized after the join):
//   [0, 8193)       : A_low diagonal k = 0..8192 (k = 8192 -> 1)
//   [8193, 16385)   : A_up diagonal  k = 0..8191
#define D_SPLIT NP1
#define D_TOT   (D_SPLIT + NN)            // 16385

#define THREADS 512

__global__ void __launch_bounds__(THREADS) relu_patch_edges(
        const float* __restrict__ lower,
        const float* __restrict__ upper,
        const float* __restrict__ alphas,
        float* __restrict__ out) {
    const int w = blockIdx.x * THREADS + threadIdx.x;
    if (w >= E_TOT) return;

    if (w < E_HEAD) {
        const int i = w & (NN - 1);
        const float l = lower[i];
        const float u = upper[i];
        float val;
        if (w < NN) {
            const float a = fminf(fmaxf(alphas[i], 0.f), 1.f);
            val = (u > 0.f) ? ((l >= 0.f) ? l : a * l) : 0.f;
        } else {
            val = (u > 0.f) ? u : 0.f;
        }
        out[w] = val;
    } else {
        const int col = w - E_HEAD;
        float val;
        if (col == NN) {
            val = 1.f;
        } else {
            const float l = lower[col];
            const float u = upper[col];
            const float d = u - l;
            const float lam = u / ((d == 0.f) ? 1.f : d);
            val = ((u > 0.f) && (l < 0.f)) ? (-lam * l) : 0.f;
        }
        out[LR0 + (size_t)col] = val;
    }
}

__global__ void __launch_bounds__(THREADS) relu_patch_diag(
        const float* __restrict__ lower,
        const float* __restrict__ upper,
        const float* __restrict__ alphas,
        float* __restrict__ out) {
    const int w = blockIdx.x * THREADS + threadIdx.x;
    if (w >= D_TOT) return;

    size_t pos;
    float  val;
    if (w < D_SPLIT) {
        const int k = w;                               // A_low diag
        if (k == NN) {
            val = 1.f;
        } else {
            const float l = lower[k];
            const float u = upper[k];
            const float a = fminf(fmaxf(alphas[k], 0.f), 1.f);
            val = (u > 0.f) ? ((l >= 0.f) ? 1.f : a) : 0.f;
        }
        pos = AB + (size_t)k * (size_t)(NP1 + 1);
    } else {
        const int k = w - D_SPLIT;                     // A_up diag
        const float l = lower[k];
        const float u = upper[k];
        const float d = u - l;
        const float lam = u / ((d == 0.f) ? 1.f : d);
        val = (u > 0.f) ? ((l >= 0.f) ? 1.f : lam) : 0.f;
        pos = AUB + (size_t)k * (size_t)(NP1 + 1);
    }
    __stcs(out + pos, val);
}

// Streams/events created once at load; no device-memory allocation.
namespace {
struct ForkCtx {
    cudaStream_t sM1, sM2, sM3, sE;
    cudaEvent_t  eRoot, eM1, eM2, eM3, eE;
    ForkCtx() {
        cudaStreamCreateWithFlags(&sM1, cudaStreamNonBlocking);
        cudaStreamCreateWithFlags(&sM2, cudaStreamNonBlocking);
        cudaStreamCreateWithFlags(&sM3, cudaStreamNonBlocking);
        cudaStreamCreateWithFlags(&sE,  cudaStreamNonBlocking);
        cudaEventCreateWithFlags(&eRoot, cudaEventDisableTiming);
        cudaEventCreateWithFlags(&eM1,   cudaEventDisableTiming);
        cudaEventCreateWithFlags(&eM2,   cudaEventDisableTiming);
        cudaEventCreateWithFlags(&eM3,   cudaEventDisableTiming);
        cudaEventCreateWithFlags(&eE,    cudaEventDisableTiming);
    }
};
ForkCtx g_f;
}

extern "C" void kernel_launch(void* const* d_in, const int* in_sizes, int n_in,
                              void* d_out, int out_size) {
    const float* lower  = (const float*)d_in[0];
    const float* upper  = (const float*)d_in[1];
    const float* alphas = (const float*)d_in[2];
    float* out = (float*)d_out;
    char*  base = (char*)d_out;

    // Fork root
    cudaEventRecord(g_f.eRoot, 0);
    cudaStreamWaitEvent(g_f.sM1, g_f.eRoot, 0);
    cudaStreamWaitEvent(g_f.sM2, g_f.eRoot, 0);
    cudaStreamWaitEvent(g_f.sM3, g_f.eRoot, 0);
    cudaStreamWaitEvent(g_f.sE,  g_f.eRoot, 0);

    // Four PARALLEL memset nodes, one quarter of the interior each.
    cudaMemsetAsync(base + MS_BASE,               0, MS_Q,  0);        // q0, stream0
    cudaMemsetAsync(base + MS_BASE + 1 * MS_Q,    0, MS_Q,  g_f.sM1);  // q1
    cudaMemsetAsync(base + MS_BASE + 2 * MS_Q,    0, MS_Q,  g_f.sM2);  // q2
    cudaMemsetAsync(base + MS_BASE + 3 * MS_Q,    0, MS_Q3, g_f.sM3);  // q3

    // Edges kernel overlaps the memsets (disjoint bytes).
    relu_patch_edges<<<(E_TOT + THREADS - 1) / THREADS, THREADS, 0, g_f.sE>>>(
        lower, upper, alphas, out);
    cudaEventRecord(g_f.eE, g_f.sE);

    // Join the three side memsets into stream0.
    cudaEventRecord(g_f.eM1, g_f.sM1);
    cudaEventRecord(g_f.eM2, g_f.sM2);
    cudaEventRecord(g_f.eM3, g_f.sM3);
    cudaStreamWaitEvent(0, g_f.eM1, 0);
    cudaStreamWaitEvent(0, g_f.eM2, 0);
    cudaStreamWaitEvent(0, g_f.eM3, 0);

    // Serialized tail: diagonals (inside the zeroed region).
    relu_patch_diag<<<(D_TOT + THREADS - 1) / THREADS, THREADS>>>(
        lower, upper, alphas, out);

    // Join edges before capture ends.
    cudaStreamWaitEvent(0, g_f.eE, 0);
}